// round 3
// baseline (speedup 1.0000x reference)
#include <cuda_runtime.h>
#include <cuda_bf16.h>

// Problem constants (fixed by setup_inputs): pred (16,54,192,192) f32,
// target (16,6,192,192) f32, loc (128,2) int32 (UNUSED by reference).
// loss = [ bce_sum(pred[:,0:18:2], target[:,0:1]) +
//          bce_sum(pred[:,1:18:2], target[:,1:2]) ] / 9
// i.e. sum over pred channels 0..17, where channel ch pairs with target
// channel (ch & 1).

namespace {
constexpr int B        = 16;
constexpr int H        = 192;
constexpr int W        = 192;
constexpr int HW       = H * W;        // 36864
constexpr int HW4      = HW / 4;       // 9216 float4 per channel slice
constexpr int NCH      = 18;           // pred channels actually read
constexpr int PRED_CH  = 54;
constexpr int TGT_CH   = 6;

constexpr int TPB      = 256;
constexpr int SPLIT    = 4;                  // hw chunks per slice
constexpr int CHUNK4   = HW4 / SPLIT;        // 2304 float4 per block
constexpr int ITERS    = CHUNK4 / TPB;       // 9 float4 per thread
constexpr int NSLICES  = B * NCH;            // 288
constexpr int NBLOCKS  = NSLICES * SPLIT;    // 1152
}

// Scratch for deterministic two-pass reduction (no device alloc allowed).
__device__ float g_partials[NBLOCKS];

__device__ __forceinline__ float bce_term(float x, float y) {
    // max(x,0) - x*y + log1p(exp(-|x|))
    float ax = fabsf(x);
    float e  = __expf(-ax);               // MUFU.EX2 path
    return fmaxf(x, 0.0f) - x * y + __logf(1.0f + e);  // MUFU.LG2 path
}

__device__ __forceinline__ float block_reduce(float acc) {
    #pragma unroll
    for (int o = 16; o > 0; o >>= 1)
        acc += __shfl_xor_sync(0xffffffffu, acc, o);
    __shared__ float s[TPB / 32];
    if ((threadIdx.x & 31) == 0) s[threadIdx.x >> 5] = acc;
    __syncthreads();
    float v = 0.0f;
    if (threadIdx.x < 32) {
        v = (threadIdx.x < TPB / 32) ? s[threadIdx.x] : 0.0f;
        #pragma unroll
        for (int o = 4; o > 0; o >>= 1)
            v += __shfl_xor_sync(0xffffffffu, v, o);
    }
    return v;  // valid in thread 0
}

__global__ __launch_bounds__(TPB)
void rpn_bce_partial(const float4* __restrict__ pred,
                     const float4* __restrict__ target) {
    const int slice = blockIdx.y;          // 0..287
    const int ch    = slice % NCH;         // pred channel 0..17
    const int b     = slice / NCH;

    const float4* __restrict__ p =
        pred + ((size_t)b * PRED_CH + ch) * HW4 + (size_t)blockIdx.x * CHUNK4;
    const float4* __restrict__ t =
        target + ((size_t)b * TGT_CH + (ch & 1)) * HW4 + (size_t)blockIdx.x * CHUNK4;

    float acc = 0.0f;
    #pragma unroll
    for (int i = 0; i < ITERS; ++i) {
        const int idx = i * TPB + threadIdx.x;
        const float4 x = __ldg(p + idx);
        const float4 y = __ldg(t + idx);
        acc += bce_term(x.x, y.x) + bce_term(x.y, y.y)
             + bce_term(x.z, y.z) + bce_term(x.w, y.w);
    }

    const float v = block_reduce(acc);
    if (threadIdx.x == 0)
        g_partials[slice * SPLIT + blockIdx.x] = v;
}

__global__ __launch_bounds__(TPB)
void rpn_bce_finalize(float* __restrict__ out) {
    float acc = 0.0f;
    #pragma unroll
    for (int i = threadIdx.x; i < NBLOCKS; i += TPB)
        acc += g_partials[i];
    const float v = block_reduce(acc);
    if (threadIdx.x == 0)
        out[0] = v * (1.0f / 9.0f);   // / NUM_OBJ_CLS
}

extern "C" void kernel_launch(void* const* d_in, const int* in_sizes, int n_in,
                              void* d_out, int out_size) {
    (void)in_sizes; (void)n_in; (void)out_size;
    const float4* pred   = (const float4*)d_in[0];
    const float4* target = (const float4*)d_in[1];
    // d_in[2] (loc) is unused by the reference.
    float* out = (float*)d_out;

    dim3 grid(SPLIT, NSLICES);
    rpn_bce_partial<<<grid, TPB>>>(pred, target);
    rpn_bce_finalize<<<1, TPB>>>(out);
}

// round 4
// speedup vs baseline: 1.0226x; 1.0226x over previous
#include <cuda_runtime.h>
#include <cuda_bf16.h>

// pred (16,54,192,192) f32, target (16,6,192,192) f32, loc unused.
// loss = [ bce_sum(pred[:,0:18:2], target[:,0:1]) +
//          bce_sum(pred[:,1:18:2], target[:,1:2]) ] / 9
// Pred channel ch (0..17) pairs with target channel (ch & 1).

namespace {
constexpr int B        = 16;
constexpr int H        = 192;
constexpr int W        = 192;
constexpr int HW       = H * W;        // 36864
constexpr int HW4      = HW / 4;       // 9216 float4 per channel slice
constexpr int NCH      = 18;
constexpr int PRED_CH  = 54;
constexpr int TGT_CH   = 6;

constexpr int TPB      = 256;
constexpr int SPLIT    = 4;                  // hw chunks per slice
constexpr int CHUNK4   = HW4 / SPLIT;        // 2304 float4 per block
constexpr int ITERS    = CHUNK4 / TPB;       // 9 float4 per thread
constexpr int NSLICES  = B * NCH;            // 288
constexpr int NBLOCKS  = NSLICES * SPLIT;    // 1152
}

// Scratch (no device allocation allowed). g_count is reset to 0 by the
// last block every launch, so graph replays are idempotent.
__device__ float        g_partials[NBLOCKS];
__device__ unsigned int g_count = 0;

__device__ __forceinline__ float bce_term(float x, float y) {
    // max(x,0) - x*y + log1p(exp(-|x|))
    float ax = fabsf(x);
    float e  = __expf(-ax);                              // MUFU.EX2
    return fmaxf(x, 0.0f) - x * y + __logf(1.0f + e);    // MUFU.LG2
}

__device__ __forceinline__ float block_reduce(float acc) {
    #pragma unroll
    for (int o = 16; o > 0; o >>= 1)
        acc += __shfl_xor_sync(0xffffffffu, acc, o);
    __shared__ float s[TPB / 32];
    if ((threadIdx.x & 31) == 0) s[threadIdx.x >> 5] = acc;
    __syncthreads();
    float v = 0.0f;
    if (threadIdx.x < 32) {
        v = (threadIdx.x < TPB / 32) ? s[threadIdx.x] : 0.0f;
        #pragma unroll
        for (int o = 4; o > 0; o >>= 1)
            v += __shfl_xor_sync(0xffffffffu, v, o);
    }
    return v;  // valid in thread 0
}

__global__ __launch_bounds__(TPB)
void rpn_bce_fused(const float4* __restrict__ pred,
                   const float4* __restrict__ target,
                   float* __restrict__ out) {
    const int bid   = blockIdx.x;          // 0..1151
    const int chunk = bid % SPLIT;
    const int slice = bid / SPLIT;         // 0..287
    const int ch    = slice % NCH;         // pred channel 0..17
    const int b     = slice / NCH;

    const float4* __restrict__ p =
        pred + ((size_t)b * PRED_CH + ch) * HW4 + (size_t)chunk * CHUNK4;
    const float4* __restrict__ t =
        target + ((size_t)b * TGT_CH + (ch & 1)) * HW4 + (size_t)chunk * CHUNK4;

    float acc = 0.0f;
    #pragma unroll
    for (int i = 0; i < ITERS; ++i) {
        const int idx = i * TPB + threadIdx.x;
        const float4 x = __ldg(p + idx);
        const float4 y = __ldg(t + idx);
        acc += bce_term(x.x, y.x) + bce_term(x.y, y.y)
             + bce_term(x.z, y.z) + bce_term(x.w, y.w);
    }

    const float v = block_reduce(acc);

    // Publish partial, then determine if this is the last block to finish.
    __shared__ bool s_last;
    if (threadIdx.x == 0) {
        g_partials[bid] = v;
        __threadfence();                               // partial visible chip-wide
        unsigned int n = atomicAdd(&g_count, 1u);
        s_last = (n == (unsigned int)(NBLOCKS - 1));
    }
    __syncthreads();

    if (s_last) {
        __threadfence();                               // acquire all partials
        // Deterministic: fixed-order strided read + fixed-shape tree reduce.
        float a = 0.0f;
        #pragma unroll
        for (int i = threadIdx.x; i < NBLOCKS; i += TPB)
            a += g_partials[i];
        const float total = block_reduce(a);
        if (threadIdx.x == 0) {
            out[0] = total * (1.0f / 9.0f);            // / NUM_OBJ_CLS
            g_count = 0;                               // reset for next replay
        }
    }
}

extern "C" void kernel_launch(void* const* d_in, const int* in_sizes, int n_in,
                              void* d_out, int out_size) {
    (void)in_sizes; (void)n_in; (void)out_size;
    const float4* pred   = (const float4*)d_in[0];
    const float4* target = (const float4*)d_in[1];
    float* out = (float*)d_out;

    rpn_bce_fused<<<NBLOCKS, TPB>>>(pred, target, out);
}